// round 12
// baseline (speedup 1.0000x reference)
#include <cuda_runtime.h>
#include <cuda_bf16.h>
#include <cstdint>

#define BATCH 2
#define NANCH 261888
#define PRE_NMS 6000
#define PRE2 1280          // prefix length for fast-path NMS
#define NW2 (PRE2 / 64)    // 20 words per prefix row
#define NW2P 21            // padded smem row stride (bank-conflict break)
#define PROP 1000
#define NMS_THR 0.7f
#define NBINS 2048
#define SCAP 12288
#define BUCKET_CAP 2048
#define SB_GRID 128

#define HS_BLOCKS 128
#define HS_THREADS 1024
#define HS_PER_THREAD 2    // float4s per thread: 128*1024*2 = 262144 >= 261888

#define SMEM_NMS (PRE2 * NW2P * 8)   // 215040 B staged mask (padded)

typedef unsigned long long u64;

// ---------------- scratch (zero at module load; re-zeroed by tail kernel) -------
__device__ int g_hist[BATCH * NBINS];
__device__ int g_offset[BATCH * NBINS];
__device__ int g_binfill[BATCH * NBINS];
__device__ int g_cutbin[BATCH];
__device__ unsigned int g_ticket;
__device__ int g_ready;
__device__ u64 g_sorted[BATCH * SCAP];
__device__ float4 g_boxes[BATCH * PRE_NMS];
__device__ u64 g_mask2[(size_t)BATCH * PRE2 * NW2];   // 400 KB prefix mask

// ---------------- helpers ----------------
__device__ __forceinline__ int score_bin(float s) {
    int b = (int)(s * (float)NBINS);
    if (b < 0) b = 0;
    if (b > NBINS - 1) b = NBINS - 1;
    return b;
}

// keep ⟺ iou > THR ⟺ (1+THR)*inter > THR*(areaR+areaC+eps)  (denominator > 0)
__device__ __forceinline__ bool iou_gt(float4 a, float aR7, float4 c, float cA7) {
    float ih = fmaxf(fminf(a.z, c.z) - fmaxf(a.x, c.x), 0.f);
    float iw = fmaxf(fminf(a.w, c.w) - fmaxf(a.y, c.y), 0.f);
    float inter = ih * iw;
    return 1.7f * inter > aR7 + cA7;
}

// ------ 1: fused histogram + suffix-scan + scatter (single read of cls) --------
__global__ void __launch_bounds__(HS_THREADS, 1)
histscatter_kernel(const float4* __restrict__ cls4) {
    __shared__ int h[BATCH * NBINS];   // 16 KB
    for (int t = threadIdx.x; t < BATCH * NBINS; t += HS_THREADS) h[t] = 0;
    __syncthreads();
    const int total4 = BATCH * NANCH / 2;   // 261888
    const int half = NANCH / 2;
    const int gsz = HS_BLOCKS * HS_THREADS; // 131072
    int tid = blockIdx.x * HS_THREADS + threadIdx.x;

    float sc[HS_PER_THREAD * 2];
#pragma unroll
    for (int u = 0; u < HS_PER_THREAD; ++u) {
        int t = tid + u * gsz;
        float y = -1.f, w = -1.f;
        if (t < total4) {
            float4 v = cls4[t];
            y = v.y; w = v.w;
            int b = t / half;
            atomicAdd(&h[b * NBINS + score_bin(y)], 1);
            atomicAdd(&h[b * NBINS + score_bin(w)], 1);
        }
        sc[u * 2 + 0] = y;
        sc[u * 2 + 1] = w;
    }
    __syncthreads();
    for (int t = threadIdx.x; t < BATCH * NBINS; t += HS_THREADS)
        if (h[t]) atomicAdd(&g_hist[t], h[t]);

    __threadfence();
    __shared__ int is_last;
    if (threadIdx.x == 0)
        is_last = (atomicAdd(&g_ticket, 1u) == HS_BLOCKS - 1) ? 1 : 0;
    __syncthreads();

    if (is_last) {
        __shared__ int sA[1024], sB[1024];
        for (int b = 0; b < BATCH; ++b) {
            int t = threadIdx.x;
            int base = b * NBINS + t * 2;
            int h0 = g_hist[base + 0], h1 = g_hist[base + 1];
            int sum = h0 + h1;
            sA[t] = sum;
            __syncthreads();
            int* src = sA; int* dst = sB;
            for (int d = 1; d < 1024; d <<= 1) {
                int v = src[t];
                if (t + d < 1024) v += src[t + d];
                dst[t] = v;
                __syncthreads();
                int* tmp = src; src = dst; dst = tmp;
            }
            int excl = src[t] - sum;
            int off1 = excl;
            int off0 = off1 + h1;
            g_offset[base + 0] = off0; g_offset[base + 1] = off1;
            if (off1 + h1 >= PRE_NMS) atomicMax(&g_cutbin[b], t * 2 + 1);
            else if (off0 + h0 >= PRE_NMS) atomicMax(&g_cutbin[b], t * 2 + 0);
            __syncthreads();
        }
        __threadfence();
        if (threadIdx.x == 0) atomicExch(&g_ready, 1);
    }

    if (threadIdx.x == 0) {
        while (atomicAdd(&g_ready, 0) == 0) __nanosleep(128);
    }
    __syncthreads();
    __threadfence();

    int cut0 = g_cutbin[0];
    int cut1 = g_cutbin[1];
#pragma unroll
    for (int u = 0; u < HS_PER_THREAD; ++u) {
        int t = tid + u * gsz;
        if (t >= total4) continue;
        int b = t / half;
        int i0 = (t - b * half) * 2;
        int cut = (b == 0) ? cut0 : cut1;
#pragma unroll
        for (int e = 0; e < 2; ++e) {
            float s = sc[u * 2 + e];
            int i = i0 + e;
            int q = score_bin(s);
            if (q >= cut) {
                int pos = g_offset[b * NBINS + q] + atomicAdd(&g_binfill[b * NBINS + q], 1);
                if (pos < SCAP) {
                    unsigned int sb = __float_as_uint(s);
                    g_sorted[b * SCAP + pos] =
                        ((u64)sb << 32) | (u64)(0xFFFFFFFFu - (unsigned)i);
                }
            }
        }
    }
}

// ---------------- 2: per-bucket sort + box decode (cutbin-relative grid) -------
__global__ void sortbox_kernel(const float* __restrict__ rpn_bbox,
                               const float* __restrict__ anchors) {
    int b = blockIdx.y;
    int cut = g_cutbin[b];
    __shared__ u64 s[BUCKET_CAP];
    for (int bin = cut + blockIdx.x; bin < NBINS; bin += SB_GRID) {
        int cnt = g_hist[b * NBINS + bin];
        if (cnt <= 0) continue;
        if (cnt > BUCKET_CAP) cnt = BUCKET_CAP;
        int off = g_offset[b * NBINS + bin];
        if (off >= PRE_NMS) continue;
        int P = 1;
        while (P < cnt) P <<= 1;
        const u64* src = g_sorted + (size_t)b * SCAP + off;
        for (int t = threadIdx.x; t < P; t += blockDim.x)
            s[t] = (t < cnt) ? src[t] : 0ULL;
        __syncthreads();
        if (cnt > 1) {
            for (int k = 2; k <= P; k <<= 1) {
                for (int j = k >> 1; j > 0; j >>= 1) {
                    for (int i = threadIdx.x; i < P; i += blockDim.x) {
                        int ixj = i ^ j;
                        if (ixj > i) {
                            bool dir = ((i & k) == 0);
                            u64 a = s[i], c = s[ixj];
                            if ((a < c) == dir) { s[i] = c; s[ixj] = a; }
                        }
                    }
                    __syncthreads();
                }
            }
        }
        for (int t = threadIdx.x; t < cnt; t += blockDim.x) {
            int rank = off + t;
            if (rank >= PRE_NMS) continue;
            unsigned int low = (unsigned int)(s[t] & 0xFFFFFFFFu);
            int idx = (int)(0xFFFFFFFFu - low);
            size_t base = ((size_t)b * NANCH + (size_t)idx) * 4;
            float a0 = anchors[base + 0], a1 = anchors[base + 1];
            float a2 = anchors[base + 2], a3 = anchors[base + 3];
            float d0 = rpn_bbox[base + 0] * 0.1f;
            float d1 = rpn_bbox[base + 1] * 0.1f;
            float d2 = rpn_bbox[base + 2] * 0.2f;
            float d3 = rpn_bbox[base + 3] * 0.2f;
            float h = a2 - a0, w = a3 - a1;
            float cy = a0 + 0.5f * h + d0 * h;
            float cx = a1 + 0.5f * w + d1 * w;
            h = h * expf(d2);
            w = w * expf(d3);
            float y1 = cy - 0.5f * h;
            float x1 = cx - 0.5f * w;
            float y2 = y1 + h;
            float x2 = x1 + w;
            y1 = fminf(fmaxf(y1, 0.f), 1.f);
            x1 = fminf(fmaxf(x1, 0.f), 1.f);
            y2 = fminf(fmaxf(y2, 0.f), 1.f);
            x2 = fminf(fmaxf(x2, 0.f), 1.f);
            g_boxes[b * PRE_NMS + rank] = make_float4(y1, x1, y2, x2);
        }
        __syncthreads();
    }
}

// -------- 3: prefix IoU bitmask (LOWER triangle: row i needs cols <= wi) -------
__global__ void __launch_bounds__(128) maskpre_kernel() {
    int b = blockIdx.z;
    int row0 = blockIdx.y * 128;
    int col0 = blockIdx.x * 64;
    if (col0 >= row0 + 128) return;   // no column <= any row-word in block
    __shared__ float4 cbox[64];
    __shared__ float cA7[64];
    int t = threadIdx.x;              // 128 threads
    if (t < 64) {
        float4 cb = g_boxes[b * PRE_NMS + col0 + t];
        cbox[t] = cb;
        cA7[t] = 0.7f * ((cb.z - cb.x) * (cb.w - cb.y) + 1e-8f);
    }
    __syncthreads();
    int r = row0 + t;
    float4 rb = g_boxes[b * PRE_NMS + r];
    float aR7 = 0.7f * ((rb.z - rb.x) * (rb.w - rb.y));
    unsigned lo = 0, hi = 0;
#pragma unroll
    for (int jj = 0; jj < 32; ++jj)
        if (iou_gt(rb, aR7, cbox[jj], cA7[jj])) lo |= (1u << jj);
#pragma unroll
    for (int jj = 0; jj < 32; ++jj)
        if (iou_gt(rb, aR7, cbox[32 + jj], cA7[32 + jj])) hi |= (1u << jj);
    g_mask2[((size_t)b * PRE2 + r) * NW2 + blockIdx.x] = ((u64)hi << 32) | lo;
}

// -- 4: NMS — smem-staged, one-pass forward substitution over word-columns -----
__global__ void __launch_bounds__(1024) nms_kernel(float* __restrict__ out) {
    if (blockIdx.x >= BATCH) {
        // cleanup blocks: re-zero scratch for the next graph replay
        int start = (blockIdx.x - BATCH) * blockDim.x + threadIdx.x;
        for (int t = start; t < BATCH * NBINS; t += 8 * blockDim.x) {
            g_hist[t] = 0;
            g_binfill[t] = 0;
        }
        if (start == 0) {
            g_cutbin[0] = 0; g_cutbin[1] = 0;
            g_ticket = 0u;
            g_ready = 0;
        }
        return;
    }
    int b = blockIdx.x;
    extern __shared__ unsigned char dynsm[];
    u64* sm64 = (u64*)dynsm;                     // [PRE2][NW2P]
    __shared__ u64 keptW[NW2];
    __shared__ u64 dw[64];
    __shared__ u64 spart[8 * 64];
    __shared__ u64 s_keptm;
    __shared__ unsigned ball[2];
    __shared__ int list[PROP];
    int tid = threadIdx.x;

    // stage mask rows into padded smem (all 32 warps)
    {
        const u64* src = g_mask2 + (size_t)b * PRE2 * NW2;
        for (int idx = tid; idx < PRE2 * NW2; idx += 1024) {
            int row = idx / NW2;
            int w = idx - row * NW2;
            sm64[row * NW2P + w] = src[idx];
        }
    }
    __syncthreads();

    int row = tid & 63;       // row within current word-column
    int part = tid >> 6;      // 0..15; parts 0..7 active in phase A
    int kc = 0;
    for (int k = 0; k < NW2; ++k) {
        const u64* rp = sm64 + (size_t)(k * 64 + row) * NW2P;
        if (part < 8) {
            // external suppression from finalized columns (8 slices/row, <=3 LDS)
            u64 s = 0;
            for (int w = part; w < k; w += 8) s |= rp[w] & keptW[w];
            spart[part * 64 + row] = s;
            if (part == 0) dw[row] = rp[k];   // diagonal word
        }
        __syncthreads();
        if (tid < 64) {
            u64 sf = 0;
#pragma unroll
            for (int p = 0; p < 8; ++p) sf |= spart[p * 64 + tid];
            unsigned bal = __ballot_sync(0xffffffffu, sf != 0ULL);
            if ((tid & 31) == 0) ball[tid >> 5] = bal;
        }
        __syncthreads();
        if (tid == 0) {
            u64 supm = ((u64)ball[1] << 32) | (u64)ball[0];
            u64 keptm0 = ~supm;
            // verify: any kept-kept suppression inside the 64x64 diagonal?
            u64 acc = 0;
#pragma unroll
            for (int t = 1; t < 64; ++t) {
                u64 m = 0ULL - ((keptm0 >> t) & 1ULL);
                acc |= dw[t] & keptm0 & ((1ULL << t) - 1ULL) & m;
            }
            u64 keptm;
            if (acc == 0ULL) {
                keptm = keptm0;          // speculation exact
            } else {
                // rare: serial greedy within the column
                keptm = 0;
                for (int t = 0; t < 64; ++t) {
                    if (!((supm >> t) & 1ULL) && ((dw[t] & keptm) == 0ULL))
                        keptm |= (1ULL << t);
                }
            }
            // trim to first (PROP - kc) kept rows
            int pc = __popcll(keptm);
            int rema = PROP - kc;
            while (pc > rema) {
                keptm &= ~(1ULL << (63 - __clzll(keptm)));
                --pc;
            }
            keptW[k] = keptm;
            s_keptm = keptm;
        }
        __syncthreads();
        u64 keptm = s_keptm;
        if (tid < 64 && ((keptm >> tid) & 1ULL)) {
            int pos = kc + __popcll(keptm & ((1ULL << tid) - 1ULL));
            list[pos] = k * 64 + tid;
        }
        kc += __popcll(keptm);
        if (kc >= PROP) break;
    }
    __syncthreads();

    const float4* bx = g_boxes + b * PRE_NMS;
    float4* o = (float4*)(out + (size_t)b * PROP * 4);
    if (kc >= PROP) {
        for (int r = tid; r < PROP; r += blockDim.x) o[r] = bx[list[r]];
        return;
    }

    // fallback: exact direct sequential NMS over all 6000 boxes (rarely taken)
    // kept arrays alias the dynamic smem (mask no longer needed)
    float4* kept = (float4*)dynsm;
    float* keptA7 = (float*)(dynsm + sizeof(float4) * PROP);
    __syncthreads();
    int kk = 0;
    for (int i = 0; i < PRE_NMS && kk < PROP; ++i) {
        float4 bi = bx[i];
        float aR7 = 0.7f * ((bi.z - bi.x) * (bi.w - bi.y));
        int sup = 0;
        for (int j = tid; j < kk; j += blockDim.x)
            if (iou_gt(bi, aR7, kept[j], keptA7[j])) sup = 1;
        sup = __syncthreads_or(sup);
        if (!sup) {
            if (tid == 0) {
                kept[kk] = bi;
                keptA7[kk] = 0.7f * ((bi.z - bi.x) * (bi.w - bi.y) + 1e-8f);
            }
            kk++;
            __syncthreads();
        }
    }
    for (int r = tid; r < PROP; r += blockDim.x) {
        float4 v = make_float4(0.f, 0.f, 0.f, 0.f);
        if (r < kk) v = kept[r];
        o[r] = v;
    }
}

// ---------------- launch ----------------
extern "C" void kernel_launch(void* const* d_in, const int* in_sizes, int n_in,
                              void* d_out, int out_size) {
    (void)in_sizes; (void)n_in; (void)out_size;
    const float4* cls4 = (const float4*)d_in[0];
    const float* rpn_bbox = (const float*)d_in[1];
    const float* anchors = (const float*)d_in[2];
    float* out = (float*)d_out;

    cudaFuncSetAttribute(nms_kernel, cudaFuncAttributeMaxDynamicSharedMemorySize,
                         SMEM_NMS);

    histscatter_kernel<<<HS_BLOCKS, HS_THREADS>>>(cls4);
    {
        dim3 grid(SB_GRID, BATCH);
        sortbox_kernel<<<grid, 128>>>(rpn_bbox, anchors);
    }
    {
        dim3 grid(NW2, PRE2 / 128, BATCH);   // (20, 10, 2)
        maskpre_kernel<<<grid, 128>>>();
    }
    nms_kernel<<<BATCH + 8, 1024, SMEM_NMS>>>(out);
}

// round 13
// speedup vs baseline: 1.6711x; 1.6711x over previous
#include <cuda_runtime.h>
#include <cuda_bf16.h>
#include <cstdint>

#define BATCH 2
#define NANCH 261888
#define PRE_NMS 6000
#define PRE2 1280          // prefix length for fast-path NMS
#define NW2 (PRE2 / 64)    // 20 words per prefix row
#define NW2P 21            // padded smem row stride (bank-conflict break)
#define PROP 1000
#define NMS_THR 0.7f
#define NBINS 2048
#define SCAP 12288
#define BUCKET_CAP 2048
#define SB_GRID 128
#define ULIST_CAP 768

#define HS_BLOCKS 128
#define HS_THREADS 1024
#define HS_PER_THREAD 2    // float4s per thread: 128*1024*2 = 262144 >= 261888

#define SMEM_NMS (PRE2 * NW2P * 8)   // 215040 B staged mask (padded)

typedef unsigned long long u64;

// ---------------- scratch (zero at module load; re-zeroed by tail kernel) -------
__device__ int g_hist[BATCH * NBINS];
__device__ int g_offset[BATCH * NBINS];
__device__ int g_binfill[BATCH * NBINS];
__device__ int g_cutbin[BATCH];
__device__ unsigned int g_ticket;
__device__ int g_ready;
__device__ u64 g_sorted[BATCH * SCAP];
__device__ float4 g_boxes[BATCH * PRE_NMS];
__device__ u64 g_mask2[(size_t)BATCH * PRE2 * NW2];   // 400 KB prefix mask

// ---------------- helpers ----------------
__device__ __forceinline__ int score_bin(float s) {
    int b = (int)(s * (float)NBINS);
    if (b < 0) b = 0;
    if (b > NBINS - 1) b = NBINS - 1;
    return b;
}

// keep ⟺ iou > THR ⟺ (1+THR)*inter > THR*(areaR+areaC+eps)  (denominator > 0)
__device__ __forceinline__ bool iou_gt(float4 a, float aR7, float4 c, float cA7) {
    float ih = fmaxf(fminf(a.z, c.z) - fmaxf(a.x, c.x), 0.f);
    float iw = fmaxf(fminf(a.w, c.w) - fmaxf(a.y, c.y), 0.f);
    float inter = ih * iw;
    return 1.7f * inter > aR7 + cA7;
}

// ------ 1: fused histogram + suffix-scan + scatter (single read of cls) --------
__global__ void __launch_bounds__(HS_THREADS, 1)
histscatter_kernel(const float4* __restrict__ cls4) {
    __shared__ int h[BATCH * NBINS];   // 16 KB
    for (int t = threadIdx.x; t < BATCH * NBINS; t += HS_THREADS) h[t] = 0;
    __syncthreads();
    const int total4 = BATCH * NANCH / 2;   // 261888
    const int half = NANCH / 2;
    const int gsz = HS_BLOCKS * HS_THREADS; // 131072
    int tid = blockIdx.x * HS_THREADS + threadIdx.x;

    float sc[HS_PER_THREAD * 2];
#pragma unroll
    for (int u = 0; u < HS_PER_THREAD; ++u) {
        int t = tid + u * gsz;
        float y = -1.f, w = -1.f;
        if (t < total4) {
            float4 v = cls4[t];
            y = v.y; w = v.w;
            int b = t / half;
            atomicAdd(&h[b * NBINS + score_bin(y)], 1);
            atomicAdd(&h[b * NBINS + score_bin(w)], 1);
        }
        sc[u * 2 + 0] = y;
        sc[u * 2 + 1] = w;
    }
    __syncthreads();
    for (int t = threadIdx.x; t < BATCH * NBINS; t += HS_THREADS)
        if (h[t]) atomicAdd(&g_hist[t], h[t]);

    __threadfence();
    __shared__ int is_last;
    if (threadIdx.x == 0)
        is_last = (atomicAdd(&g_ticket, 1u) == HS_BLOCKS - 1) ? 1 : 0;
    __syncthreads();

    if (is_last) {
        __shared__ int sA[1024], sB[1024];
        for (int b = 0; b < BATCH; ++b) {
            int t = threadIdx.x;
            int base = b * NBINS + t * 2;
            int h0 = g_hist[base + 0], h1 = g_hist[base + 1];
            int sum = h0 + h1;
            sA[t] = sum;
            __syncthreads();
            int* src = sA; int* dst = sB;
            for (int d = 1; d < 1024; d <<= 1) {
                int v = src[t];
                if (t + d < 1024) v += src[t + d];
                dst[t] = v;
                __syncthreads();
                int* tmp = src; src = dst; dst = tmp;
            }
            int excl = src[t] - sum;
            int off1 = excl;
            int off0 = off1 + h1;
            g_offset[base + 0] = off0; g_offset[base + 1] = off1;
            if (off1 + h1 >= PRE_NMS) atomicMax(&g_cutbin[b], t * 2 + 1);
            else if (off0 + h0 >= PRE_NMS) atomicMax(&g_cutbin[b], t * 2 + 0);
            __syncthreads();
        }
        __threadfence();
        if (threadIdx.x == 0) atomicExch(&g_ready, 1);
    }

    if (threadIdx.x == 0) {
        while (atomicAdd(&g_ready, 0) == 0) __nanosleep(128);
    }
    __syncthreads();
    __threadfence();

    int cut0 = g_cutbin[0];
    int cut1 = g_cutbin[1];
#pragma unroll
    for (int u = 0; u < HS_PER_THREAD; ++u) {
        int t = tid + u * gsz;
        if (t >= total4) continue;
        int b = t / half;
        int i0 = (t - b * half) * 2;
        int cut = (b == 0) ? cut0 : cut1;
#pragma unroll
        for (int e = 0; e < 2; ++e) {
            float s = sc[u * 2 + e];
            int i = i0 + e;
            int q = score_bin(s);
            if (q >= cut) {
                int pos = g_offset[b * NBINS + q] + atomicAdd(&g_binfill[b * NBINS + q], 1);
                if (pos < SCAP) {
                    unsigned int sb = __float_as_uint(s);
                    g_sorted[b * SCAP + pos] =
                        ((u64)sb << 32) | (u64)(0xFFFFFFFFu - (unsigned)i);
                }
            }
        }
    }
}

// ---------------- 2: per-bucket sort + box decode (cutbin-relative grid) -------
__global__ void sortbox_kernel(const float* __restrict__ rpn_bbox,
                               const float* __restrict__ anchors) {
    int b = blockIdx.y;
    int cut = g_cutbin[b];
    __shared__ u64 s[BUCKET_CAP];
    for (int bin = cut + blockIdx.x; bin < NBINS; bin += SB_GRID) {
        int cnt = g_hist[b * NBINS + bin];
        if (cnt <= 0) continue;
        if (cnt > BUCKET_CAP) cnt = BUCKET_CAP;
        int off = g_offset[b * NBINS + bin];
        if (off >= PRE_NMS) continue;
        int P = 1;
        while (P < cnt) P <<= 1;
        const u64* src = g_sorted + (size_t)b * SCAP + off;
        for (int t = threadIdx.x; t < P; t += blockDim.x)
            s[t] = (t < cnt) ? src[t] : 0ULL;
        __syncthreads();
        if (cnt > 1) {
            for (int k = 2; k <= P; k <<= 1) {
                for (int j = k >> 1; j > 0; j >>= 1) {
                    for (int i = threadIdx.x; i < P; i += blockDim.x) {
                        int ixj = i ^ j;
                        if (ixj > i) {
                            bool dir = ((i & k) == 0);
                            u64 a = s[i], c = s[ixj];
                            if ((a < c) == dir) { s[i] = c; s[ixj] = a; }
                        }
                    }
                    __syncthreads();
                }
            }
        }
        for (int t = threadIdx.x; t < cnt; t += blockDim.x) {
            int rank = off + t;
            if (rank >= PRE_NMS) continue;
            unsigned int low = (unsigned int)(s[t] & 0xFFFFFFFFu);
            int idx = (int)(0xFFFFFFFFu - low);
            size_t base = ((size_t)b * NANCH + (size_t)idx) * 4;
            float a0 = anchors[base + 0], a1 = anchors[base + 1];
            float a2 = anchors[base + 2], a3 = anchors[base + 3];
            float d0 = rpn_bbox[base + 0] * 0.1f;
            float d1 = rpn_bbox[base + 1] * 0.1f;
            float d2 = rpn_bbox[base + 2] * 0.2f;
            float d3 = rpn_bbox[base + 3] * 0.2f;
            float h = a2 - a0, w = a3 - a1;
            float cy = a0 + 0.5f * h + d0 * h;
            float cx = a1 + 0.5f * w + d1 * w;
            h = h * expf(d2);
            w = w * expf(d3);
            float y1 = cy - 0.5f * h;
            float x1 = cx - 0.5f * w;
            float y2 = y1 + h;
            float x2 = x1 + w;
            y1 = fminf(fmaxf(y1, 0.f), 1.f);
            x1 = fminf(fmaxf(x1, 0.f), 1.f);
            y2 = fminf(fmaxf(y2, 0.f), 1.f);
            x2 = fminf(fmaxf(x2, 0.f), 1.f);
            g_boxes[b * PRE_NMS + rank] = make_float4(y1, x1, y2, x2);
        }
        __syncthreads();
    }
}

// -------- 3: prefix IoU bitmask (LOWER triangle: row i needs cols <= wi) -------
__global__ void __launch_bounds__(128) maskpre_kernel() {
    int b = blockIdx.z;
    int row0 = blockIdx.y * 128;
    int col0 = blockIdx.x * 64;
    if (col0 >= row0 + 128) return;   // no column <= any row-word in block
    __shared__ float4 cbox[64];
    __shared__ float cA7[64];
    int t = threadIdx.x;              // 128 threads
    if (t < 64) {
        float4 cb = g_boxes[b * PRE_NMS + col0 + t];
        cbox[t] = cb;
        cA7[t] = 0.7f * ((cb.z - cb.x) * (cb.w - cb.y) + 1e-8f);
    }
    __syncthreads();
    int r = row0 + t;
    float4 rb = g_boxes[b * PRE_NMS + r];
    float aR7 = 0.7f * ((rb.z - rb.x) * (rb.w - rb.y));
    unsigned lo = 0, hi = 0;
#pragma unroll
    for (int jj = 0; jj < 32; ++jj)
        if (iou_gt(rb, aR7, cbox[jj], cA7[jj])) lo |= (1u << jj);
#pragma unroll
    for (int jj = 0; jj < 32; ++jj)
        if (iou_gt(rb, aR7, cbox[32 + jj], cA7[32 + jj])) hi |= (1u << jj);
    g_mask2[((size_t)b * PRE2 + r) * NW2 + blockIdx.x] = ((u64)hi << 32) | lo;
}

// -- 4: NMS — certain/uncertain split: 1 parallel pass + tiny serial tail ------
__global__ void __launch_bounds__(256) nms_kernel(float* __restrict__ out) {
    if (blockIdx.x >= BATCH) {
        // cleanup blocks: re-zero scratch for the next graph replay
        int start = (blockIdx.x - BATCH) * blockDim.x + threadIdx.x;
        for (int t = start; t < BATCH * NBINS; t += 8 * blockDim.x) {
            g_hist[t] = 0;
            g_binfill[t] = 0;
        }
        if (start == 0) {
            g_cutbin[0] = 0; g_cutbin[1] = 0;
            g_ticket = 0u;
            g_ready = 0;
        }
        return;
    }
    int b = blockIdx.x;
    extern __shared__ unsigned char dynsm[];
    u64* sm64 = (u64*)dynsm;                     // [PRE2][NW2P]
    __shared__ unsigned kw32[NW2 * 2];           // certain-kept halves
    __shared__ unsigned un32[NW2 * 2];           // uncertain halves
    __shared__ u64 keptW[NW2];
    __shared__ short ulist[ULIST_CAP];
    __shared__ int s_U, s_kc;
    __shared__ int wpfx[NW2];
    __shared__ int list[PROP];
    int tid = threadIdx.x;

    // stage mask rows into padded smem
    {
        const u64* src = g_mask2 + (size_t)b * PRE2 * NW2;
        for (int idx = tid; idx < PRE2 * NW2; idx += 256) {
            int row = idx / NW2;
            int w = idx - row * NW2;
            sm64[row * NW2P + w] = src[idx];
        }
    }
    __syncthreads();

    // pass 1: sup0[i] = any earlier row overlaps i (unconditional)
#pragma unroll
    for (int r = 0; r < PRE2 / 256; ++r) {
        int i = r * 256 + tid;
        int wi = i >> 6;
        const u64* rp = sm64 + (size_t)i * NW2P;
        u64 sup = 0;
        for (int w = 0; w < wi; ++w) sup |= rp[w];
        sup |= rp[wi] & ((1ULL << (i & 63)) - 1ULL);
        unsigned bal = __ballot_sync(0xffffffffu, sup != 0ULL);
        if ((tid & 31) == 0) {
            int h = r * 8 + (tid >> 5);  // 32-bit half index, rows in order
            un32[h] = bal;
            kw32[h] = ~bal;
        }
    }
    __syncthreads();
    if (tid < NW2)
        keptW[tid] = (u64)kw32[2 * tid] | ((u64)kw32[2 * tid + 1] << 32);
    if (tid == 0) {
        int n = 0;
        for (int w = 0; w < NW2 && n <= ULIST_CAP; ++w) {
            u64 m = (u64)un32[2 * w] | ((u64)un32[2 * w + 1] << 32);
            while (m && n < ULIST_CAP) {
                int bit = __ffsll((long long)m) - 1;
                ulist[n++] = (short)(w * 64 + bit);
                m &= m - 1;
            }
            if (m) n = ULIST_CAP + 1;   // overflow: force fallback
        }
        s_U = n;
    }
    __syncthreads();

    int U = s_U;
    bool resolved = (U <= ULIST_CAP);
    if (resolved && tid < 32) {
        // serial tail: resolve uncertain rows in rank order (one warp)
        int lane = tid;
        u64 kw = (lane < NW2) ? keptW[lane] : 0ULL;
        for (int u = 0; u < U; ++u) {
            int i = ulist[u];
            int wi = i >> 6;
            u64 cur = (lane < NW2) ? sm64[(size_t)i * NW2P + lane] : 0ULL;
            u64 m = (lane < wi) ? cur
                   : ((lane == wi) ? (cur & ((1ULL << (i & 63)) - 1ULL)) : 0ULL);
            bool sup = __any_sync(0xffffffffu, (m & kw) != 0ULL);
            if (!sup && lane == wi) kw |= (1ULL << (i & 63));
        }
        if (lane < NW2) keptW[lane] = kw;
    }
    __syncthreads();

    if (tid == 0) {
        if (!resolved) {
            s_kc = 0;                   // exact fallback will handle it
        } else {
            int acc = 0;
            for (int w = 0; w < NW2; ++w) { wpfx[w] = acc; acc += __popcll(keptW[w]); }
            s_kc = acc;
        }
    }
    __syncthreads();

    int kc = s_kc;
    const float4* bx = g_boxes + b * PRE_NMS;
    float4* o = (float4*)(out + (size_t)b * PROP * 4);
    if (kc >= PROP) {
        for (int i = tid; i < PRE2; i += 256) {
            int wi = i >> 6;
            u64 kwv = keptW[wi];
            if ((kwv >> (i & 63)) & 1ULL) {
                int pos = wpfx[wi] + __popcll(kwv & ((1ULL << (i & 63)) - 1ULL));
                if (pos < PROP) list[pos] = i;
            }
        }
        __syncthreads();
        for (int r = tid; r < PROP; r += 256) o[r] = bx[list[r]];
        return;
    }

    // fallback: exact direct sequential NMS over all 6000 boxes (rarely taken)
    float4* kept = (float4*)dynsm;
    float* keptA7 = (float*)(dynsm + sizeof(float4) * PROP);
    __syncthreads();
    int kk = 0;
    for (int i = 0; i < PRE_NMS && kk < PROP; ++i) {
        float4 bi = bx[i];
        float aR7 = 0.7f * ((bi.z - bi.x) * (bi.w - bi.y));
        int sup = 0;
        for (int j = tid; j < kk; j += 256)
            if (iou_gt(bi, aR7, kept[j], keptA7[j])) sup = 1;
        sup = __syncthreads_or(sup);
        if (!sup) {
            if (tid == 0) {
                kept[kk] = bi;
                keptA7[kk] = 0.7f * ((bi.z - bi.x) * (bi.w - bi.y) + 1e-8f);
            }
            kk++;
            __syncthreads();
        }
    }
    for (int r = tid; r < PROP; r += 256) {
        float4 v = make_float4(0.f, 0.f, 0.f, 0.f);
        if (r < kk) v = kept[r];
        o[r] = v;
    }
}

// ---------------- launch ----------------
extern "C" void kernel_launch(void* const* d_in, const int* in_sizes, int n_in,
                              void* d_out, int out_size) {
    (void)in_sizes; (void)n_in; (void)out_size;
    const float4* cls4 = (const float4*)d_in[0];
    const float* rpn_bbox = (const float*)d_in[1];
    const float* anchors = (const float*)d_in[2];
    float* out = (float*)d_out;

    cudaFuncSetAttribute(nms_kernel, cudaFuncAttributeMaxDynamicSharedMemorySize,
                         SMEM_NMS);

    histscatter_kernel<<<HS_BLOCKS, HS_THREADS>>>(cls4);
    {
        dim3 grid(SB_GRID, BATCH);
        sortbox_kernel<<<grid, 128>>>(rpn_bbox, anchors);
    }
    {
        dim3 grid(NW2, PRE2 / 128, BATCH);   // (20, 10, 2)
        maskpre_kernel<<<grid, 128>>>();
    }
    nms_kernel<<<BATCH + 8, 256, SMEM_NMS>>>(out);
}

// round 15
// speedup vs baseline: 2.0221x; 1.2100x over previous
#include <cuda_runtime.h>
#include <cuda_bf16.h>
#include <cstdint>

#define BATCH 2
#define NANCH 261888
#define PRE_NMS 6000
#define PRE2 1280          // prefix length for fast-path NMS
#define NW2 (PRE2 / 64)    // 20 words per prefix row
#define PROP 1000
#define NMS_THR 0.7f
#define NBINS 2048
#define SCAP 12288
#define BUCKET_CAP 2048
#define SB_GRID 128
#define UCAP 512           // max uncertain rows handled by fast path

#define HS_BLOCKS 128
#define HS_THREADS 1024
#define HS_PER_THREAD 2    // float4s per thread: 128*1024*2 = 262144 >= 261888

#define SMEM_NMS (UCAP * NW2 * 8)   // 81920 B gathered uncertain rows

typedef unsigned long long u64;

// ---------------- scratch (zero at module load; re-zeroed across launches) ------
__device__ int g_hist[BATCH * NBINS];
__device__ int g_offset[BATCH * NBINS];
__device__ int g_binfill[BATCH * NBINS];
__device__ int g_cutbin[BATCH];
__device__ unsigned int g_ticket;
__device__ int g_ready;
__device__ unsigned g_unc[BATCH * (PRE2 / 32)];   // uncertain-row bitmap (80 words)
__device__ u64 g_sorted[BATCH * SCAP];
__device__ float4 g_boxes[BATCH * PRE_NMS];
__device__ u64 g_mask2[(size_t)BATCH * PRE2 * NW2];   // 400 KB prefix mask

// ---------------- helpers ----------------
__device__ __forceinline__ int score_bin(float s) {
    int b = (int)(s * (float)NBINS);
    if (b < 0) b = 0;
    if (b > NBINS - 1) b = NBINS - 1;
    return b;
}

// keep ⟺ iou > THR ⟺ (1+THR)*inter > THR*(areaR+areaC+eps)  (denominator > 0)
__device__ __forceinline__ bool iou_gt(float4 a, float aR7, float4 c, float cA7) {
    float ih = fmaxf(fminf(a.z, c.z) - fmaxf(a.x, c.x), 0.f);
    float iw = fmaxf(fminf(a.w, c.w) - fmaxf(a.y, c.y), 0.f);
    float inter = ih * iw;
    return 1.7f * inter > aR7 + cA7;
}

// ------ 1: fused histogram + suffix-scan + scatter (single read of cls) --------
// Also zeroes g_unc for this replay (written by maskpre two launches later —
// strictly ordered, no race; redundant zero-writes across blocks are benign).
__global__ void __launch_bounds__(HS_THREADS, 1)
histscatter_kernel(const float4* __restrict__ cls4) {
    if (threadIdx.x < BATCH * (PRE2 / 32))
        g_unc[threadIdx.x] = 0u;
    __shared__ int h[BATCH * NBINS];   // 16 KB
    for (int t = threadIdx.x; t < BATCH * NBINS; t += HS_THREADS) h[t] = 0;
    __syncthreads();
    const int total4 = BATCH * NANCH / 2;   // 261888
    const int half = NANCH / 2;
    const int gsz = HS_BLOCKS * HS_THREADS; // 131072
    int tid = blockIdx.x * HS_THREADS + threadIdx.x;

    float sc[HS_PER_THREAD * 2];
#pragma unroll
    for (int u = 0; u < HS_PER_THREAD; ++u) {
        int t = tid + u * gsz;
        float y = -1.f, w = -1.f;
        if (t < total4) {
            float4 v = cls4[t];
            y = v.y; w = v.w;
            int b = t / half;
            atomicAdd(&h[b * NBINS + score_bin(y)], 1);
            atomicAdd(&h[b * NBINS + score_bin(w)], 1);
        }
        sc[u * 2 + 0] = y;
        sc[u * 2 + 1] = w;
    }
    __syncthreads();
    for (int t = threadIdx.x; t < BATCH * NBINS; t += HS_THREADS)
        if (h[t]) atomicAdd(&g_hist[t], h[t]);

    __threadfence();
    __shared__ int is_last;
    if (threadIdx.x == 0)
        is_last = (atomicAdd(&g_ticket, 1u) == HS_BLOCKS - 1) ? 1 : 0;
    __syncthreads();

    if (is_last) {
        __shared__ int sA[1024], sB[1024];
        for (int b = 0; b < BATCH; ++b) {
            int t = threadIdx.x;
            int base = b * NBINS + t * 2;
            int h0 = g_hist[base + 0], h1 = g_hist[base + 1];
            int sum = h0 + h1;
            sA[t] = sum;
            __syncthreads();
            int* src = sA; int* dst = sB;
            for (int d = 1; d < 1024; d <<= 1) {
                int v = src[t];
                if (t + d < 1024) v += src[t + d];
                dst[t] = v;
                __syncthreads();
                int* tmp = src; src = dst; dst = tmp;
            }
            int excl = src[t] - sum;
            int off1 = excl;
            int off0 = off1 + h1;
            g_offset[base + 0] = off0; g_offset[base + 1] = off1;
            if (off1 + h1 >= PRE_NMS) atomicMax(&g_cutbin[b], t * 2 + 1);
            else if (off0 + h0 >= PRE_NMS) atomicMax(&g_cutbin[b], t * 2 + 0);
            __syncthreads();
        }
        __threadfence();
        if (threadIdx.x == 0) atomicExch(&g_ready, 1);
    }

    if (threadIdx.x == 0) {
        while (atomicAdd(&g_ready, 0) == 0) __nanosleep(128);
    }
    __syncthreads();
    __threadfence();

    int cut0 = g_cutbin[0];
    int cut1 = g_cutbin[1];
#pragma unroll
    for (int u = 0; u < HS_PER_THREAD; ++u) {
        int t = tid + u * gsz;
        if (t >= total4) continue;
        int b = t / half;
        int i0 = (t - b * half) * 2;
        int cut = (b == 0) ? cut0 : cut1;
#pragma unroll
        for (int e = 0; e < 2; ++e) {
            float s = sc[u * 2 + e];
            int i = i0 + e;
            int q = score_bin(s);
            if (q >= cut) {
                int pos = g_offset[b * NBINS + q] + atomicAdd(&g_binfill[b * NBINS + q], 1);
                if (pos < SCAP) {
                    unsigned int sb = __float_as_uint(s);
                    g_sorted[b * SCAP + pos] =
                        ((u64)sb << 32) | (u64)(0xFFFFFFFFu - (unsigned)i);
                }
            }
        }
    }
}

// ---------------- 2: per-bucket sort + box decode (cutbin-relative grid) -------
__global__ void sortbox_kernel(const float* __restrict__ rpn_bbox,
                               const float* __restrict__ anchors) {
    int b = blockIdx.y;
    int cut = g_cutbin[b];
    __shared__ u64 s[BUCKET_CAP];
    for (int bin = cut + blockIdx.x; bin < NBINS; bin += SB_GRID) {
        int cnt = g_hist[b * NBINS + bin];
        if (cnt <= 0) continue;
        if (cnt > BUCKET_CAP) cnt = BUCKET_CAP;
        int off = g_offset[b * NBINS + bin];
        if (off >= PRE_NMS) continue;
        int P = 1;
        while (P < cnt) P <<= 1;
        const u64* src = g_sorted + (size_t)b * SCAP + off;
        for (int t = threadIdx.x; t < P; t += blockDim.x)
            s[t] = (t < cnt) ? src[t] : 0ULL;
        __syncthreads();
        if (cnt > 1) {
            for (int k = 2; k <= P; k <<= 1) {
                for (int j = k >> 1; j > 0; j >>= 1) {
                    for (int i = threadIdx.x; i < P; i += blockDim.x) {
                        int ixj = i ^ j;
                        if (ixj > i) {
                            bool dir = ((i & k) == 0);
                            u64 a = s[i], c = s[ixj];
                            if ((a < c) == dir) { s[i] = c; s[ixj] = a; }
                        }
                    }
                    __syncthreads();
                }
            }
        }
        for (int t = threadIdx.x; t < cnt; t += blockDim.x) {
            int rank = off + t;
            if (rank >= PRE_NMS) continue;
            unsigned int low = (unsigned int)(s[t] & 0xFFFFFFFFu);
            int idx = (int)(0xFFFFFFFFu - low);
            size_t base = ((size_t)b * NANCH + (size_t)idx) * 4;
            float a0 = anchors[base + 0], a1 = anchors[base + 1];
            float a2 = anchors[base + 2], a3 = anchors[base + 3];
            float d0 = rpn_bbox[base + 0] * 0.1f;
            float d1 = rpn_bbox[base + 1] * 0.1f;
            float d2 = rpn_bbox[base + 2] * 0.2f;
            float d3 = rpn_bbox[base + 3] * 0.2f;
            float h = a2 - a0, w = a3 - a1;
            float cy = a0 + 0.5f * h + d0 * h;
            float cx = a1 + 0.5f * w + d1 * w;
            h = h * expf(d2);
            w = w * expf(d3);
            float y1 = cy - 0.5f * h;
            float x1 = cx - 0.5f * w;
            float y2 = y1 + h;
            float x2 = x1 + w;
            y1 = fminf(fmaxf(y1, 0.f), 1.f);
            x1 = fminf(fmaxf(x1, 0.f), 1.f);
            y2 = fminf(fmaxf(y2, 0.f), 1.f);
            x2 = fminf(fmaxf(x2, 0.f), 1.f);
            g_boxes[b * PRE_NMS + rank] = make_float4(y1, x1, y2, x2);
        }
        __syncthreads();
    }
}

// -- 3: prefix IoU bitmask + uncertain-row classification (lower triangle) ------
__global__ void __launch_bounds__(128) maskpre_kernel() {
    int b = blockIdx.z;
    int row0 = blockIdx.y * 128;
    int col0 = blockIdx.x * 64;
    if (col0 >= row0 + 128) return;   // no column <= any row-word in block
    __shared__ float4 cbox[64];
    __shared__ float cA7[64];
    int t = threadIdx.x;              // 128 threads
    if (t < 64) {
        float4 cb = g_boxes[b * PRE_NMS + col0 + t];
        cbox[t] = cb;
        cA7[t] = 0.7f * ((cb.z - cb.x) * (cb.w - cb.y) + 1e-8f);
    }
    __syncthreads();
    int r = row0 + t;
    float4 rb = g_boxes[b * PRE_NMS + r];
    float aR7 = 0.7f * ((rb.z - rb.x) * (rb.w - rb.y));
    unsigned lo = 0, hi = 0;
#pragma unroll
    for (int jj = 0; jj < 32; ++jj)
        if (iou_gt(rb, aR7, cbox[jj], cA7[jj])) lo |= (1u << jj);
#pragma unroll
    for (int jj = 0; jj < 32; ++jj)
        if (iou_gt(rb, aR7, cbox[32 + jj], cA7[32 + jj])) hi |= (1u << jj);
    u64 word = ((u64)hi << 32) | lo;
    g_mask2[((size_t)b * PRE2 + r) * NW2 + blockIdx.x] = word;
    // classify: any lower-triangle overlap -> row is "uncertain"
    int wi = r >> 6, k = blockIdx.x;
    u64 lower = (k < wi) ? word
              : ((k == wi) ? (word & ((1ULL << (r & 63)) - 1ULL)) : 0ULL);
    if (lower != 0ULL)
        atomicOr(&g_unc[b * (PRE2 / 32) + (r >> 5)], 1u << (r & 31));
}

// -- 4: NMS — certain rows free; gather + serially resolve uncertain rows only --
__global__ void __launch_bounds__(256) nms_kernel(float* __restrict__ out) {
    if (blockIdx.x >= BATCH) {
        // cleanup blocks: re-zero scratch read by EARLIER kernels of the NEXT
        // replay only (cross-launch ordered; g_unc is NOT touched here — it is
        // zeroed in histscatter to avoid the same-launch read/write race).
        int start = (blockIdx.x - BATCH) * blockDim.x + threadIdx.x;
        for (int t = start; t < BATCH * NBINS; t += 8 * blockDim.x) {
            g_hist[t] = 0;
            g_binfill[t] = 0;
        }
        if (start == 0) {
            g_cutbin[0] = 0; g_cutbin[1] = 0;
            g_ticket = 0u;
            g_ready = 0;
        }
        return;
    }
    int b = blockIdx.x;
    extern __shared__ unsigned char dynsm[];
    u64* urows = (u64*)dynsm;          // [UCAP][NW2] gathered uncertain rows
    __shared__ u64 keptW[NW2];
    __shared__ short ulist[UCAP];
    __shared__ int s_U, s_kc;
    __shared__ int wpfx[NW2];
    __shared__ int list[PROP];
    int tid = threadIdx.x;

    // build keptW (certain rows kept) and the ordered uncertain list
    if (tid == 0) {
        int n = 0;
        for (int w = 0; w < NW2; ++w) {
            unsigned u0 = g_unc[b * (PRE2 / 32) + 2 * w];
            unsigned u1 = g_unc[b * (PRE2 / 32) + 2 * w + 1];
            u64 un = (u64)u0 | ((u64)u1 << 32);
            keptW[w] = ~un;
            while (un && n < UCAP) {
                int bit = __ffsll((long long)un) - 1;
                ulist[n++] = (short)(w * 64 + bit);
                un &= un - 1;
            }
            if (un) { n = UCAP + 1; break; }   // overflow -> fallback
        }
        s_U = n;
    }
    __syncthreads();
    int U = s_U;
    bool resolved = (U <= UCAP);

    if (resolved) {
        // gather uncertain rows' mask words from L2 (parallel, ~U*20 loads)
        const u64* M = g_mask2 + (size_t)b * PRE2 * NW2;
        for (int idx = tid; idx < U * NW2; idx += 256) {
            int u = idx / NW2;
            int w = idx - u * NW2;
            urows[u * NW2 + w] = M[(size_t)ulist[u] * NW2 + w];
        }
        __syncthreads();
        if (tid < 32) {
            // serial tail: resolve uncertain rows in rank order (one warp)
            int lane = tid;
            u64 kw = (lane < NW2) ? keptW[lane] : 0ULL;
            for (int u = 0; u < U; ++u) {
                int i = ulist[u];
                int wi = i >> 6;
                u64 cur = (lane < NW2) ? urows[u * NW2 + lane] : 0ULL;
                u64 m = (lane < wi) ? cur
                       : ((lane == wi) ? (cur & ((1ULL << (i & 63)) - 1ULL)) : 0ULL);
                bool sup = __any_sync(0xffffffffu, (m & kw) != 0ULL);
                if (!sup && lane == wi) kw |= (1ULL << (i & 63));
            }
            if (lane < NW2) keptW[lane] = kw;
        }
    }
    __syncthreads();

    if (tid == 0) {
        if (!resolved) {
            s_kc = 0;                   // exact fallback will handle it
        } else {
            int acc = 0;
            for (int w = 0; w < NW2; ++w) { wpfx[w] = acc; acc += __popcll(keptW[w]); }
            s_kc = acc;
        }
    }
    __syncthreads();

    int kc = s_kc;
    const float4* bx = g_boxes + b * PRE_NMS;
    float4* o = (float4*)(out + (size_t)b * PROP * 4);
    if (kc >= PROP) {
        for (int i = tid; i < PRE2; i += 256) {
            int wi = i >> 6;
            u64 kwv = keptW[wi];
            if ((kwv >> (i & 63)) & 1ULL) {
                int pos = wpfx[wi] + __popcll(kwv & ((1ULL << (i & 63)) - 1ULL));
                if (pos < PROP) list[pos] = i;
            }
        }
        __syncthreads();
        for (int r = tid; r < PROP; r += 256) o[r] = bx[list[r]];
        return;
    }

    // fallback: exact direct sequential NMS over all 6000 boxes (rarely taken)
    float4* kept = (float4*)dynsm;
    float* keptA7 = (float*)(dynsm + sizeof(float4) * PROP);
    __syncthreads();
    int kk = 0;
    for (int i = 0; i < PRE_NMS && kk < PROP; ++i) {
        float4 bi = bx[i];
        float aR7 = 0.7f * ((bi.z - bi.x) * (bi.w - bi.y));
        int sup = 0;
        for (int j = tid; j < kk; j += 256)
            if (iou_gt(bi, aR7, kept[j], keptA7[j])) sup = 1;
        sup = __syncthreads_or(sup);
        if (!sup) {
            if (tid == 0) {
                kept[kk] = bi;
                keptA7[kk] = 0.7f * ((bi.z - bi.x) * (bi.w - bi.y) + 1e-8f);
            }
            kk++;
            __syncthreads();
        }
    }
    for (int r = tid; r < PROP; r += 256) {
        float4 v = make_float4(0.f, 0.f, 0.f, 0.f);
        if (r < kk) v = kept[r];
        o[r] = v;
    }
}

// ---------------- launch ----------------
extern "C" void kernel_launch(void* const* d_in, const int* in_sizes, int n_in,
                              void* d_out, int out_size) {
    (void)in_sizes; (void)n_in; (void)out_size;
    const float4* cls4 = (const float4*)d_in[0];
    const float* rpn_bbox = (const float*)d_in[1];
    const float* anchors = (const float*)d_in[2];
    float* out = (float*)d_out;

    cudaFuncSetAttribute(nms_kernel, cudaFuncAttributeMaxDynamicSharedMemorySize,
                         SMEM_NMS);

    histscatter_kernel<<<HS_BLOCKS, HS_THREADS>>>(cls4);
    {
        dim3 grid(SB_GRID, BATCH);
        sortbox_kernel<<<grid, 128>>>(rpn_bbox, anchors);
    }
    {
        dim3 grid(NW2, PRE2 / 128, BATCH);   // (20, 10, 2)
        maskpre_kernel<<<grid, 128>>>();
    }
    nms_kernel<<<BATCH + 8, 256, SMEM_NMS>>>(out);
}

// round 16
// speedup vs baseline: 2.0238x; 1.0009x over previous
#include <cuda_runtime.h>
#include <cuda_bf16.h>
#include <cstdint>

#define BATCH 2
#define NANCH 261888
#define PRE_NMS 6000
#define PRE2 1280          // prefix length for fast-path NMS
#define NW2 (PRE2 / 64)    // 20 words per prefix row
#define PROP 1000
#define NMS_THR 0.7f
#define NBINS 2048
#define SCAP 12288
#define BUCKET_CAP 2048
#define SB_GRID 128
#define UCAP 512           // max uncertain rows handled by fast path

#define HS_BLOCKS 128
#define HS_THREADS 1024
#define HS_PER_THREAD 2    // float4s per thread: 128*1024*2 = 262144 >= 261888

#define SMEM_NMS (UCAP * NW2 * 8)   // 81920 B gathered uncertain rows

typedef unsigned long long u64;

// ---------------- scratch (zero at module load; re-zeroed across launches) ------
__device__ int g_hist[BATCH * NBINS];
__device__ int g_offset[BATCH * NBINS];
__device__ int g_binfill[BATCH * NBINS];
__device__ int g_cutbin[BATCH];
__device__ unsigned int g_ticket;
__device__ int g_ready;
__device__ unsigned g_unc[BATCH * (PRE2 / 32)];   // uncertain-row bitmap (80 words)
__device__ u64 g_sorted[BATCH * SCAP];
__device__ float4 g_boxes[BATCH * PRE_NMS];
__device__ u64 g_mask2[(size_t)BATCH * PRE2 * NW2];   // 400 KB prefix mask

// ---------------- helpers ----------------
__device__ __forceinline__ int score_bin(float s) {
    int b = (int)(s * (float)NBINS);
    if (b < 0) b = 0;
    if (b > NBINS - 1) b = NBINS - 1;
    return b;
}

// keep ⟺ iou > THR ⟺ (1+THR)*inter > THR*(areaR+areaC+eps)  (denominator > 0)
__device__ __forceinline__ bool iou_gt(float4 a, float aR7, float4 c, float cA7) {
    float ih = fmaxf(fminf(a.z, c.z) - fmaxf(a.x, c.x), 0.f);
    float iw = fmaxf(fminf(a.w, c.w) - fmaxf(a.y, c.y), 0.f);
    float inter = ih * iw;
    return 1.7f * inter > aR7 + cA7;
}

// ------ 1: fused histogram + suffix-scan + scatter (single read of cls) --------
// Also zeroes g_unc for this replay (written by maskpre two launches later —
// strictly ordered, no race; redundant zero-writes across blocks are benign).
__global__ void __launch_bounds__(HS_THREADS, 1)
histscatter_kernel(const float4* __restrict__ cls4) {
    if (threadIdx.x < BATCH * (PRE2 / 32))
        g_unc[threadIdx.x] = 0u;
    __shared__ int h[BATCH * NBINS];   // 16 KB
    for (int t = threadIdx.x; t < BATCH * NBINS; t += HS_THREADS) h[t] = 0;
    __syncthreads();
    const int total4 = BATCH * NANCH / 2;   // 261888
    const int half = NANCH / 2;
    const int gsz = HS_BLOCKS * HS_THREADS; // 131072
    int tid = blockIdx.x * HS_THREADS + threadIdx.x;

    float sc[HS_PER_THREAD * 2];
#pragma unroll
    for (int u = 0; u < HS_PER_THREAD; ++u) {
        int t = tid + u * gsz;
        float y = -1.f, w = -1.f;
        if (t < total4) {
            float4 v = cls4[t];
            y = v.y; w = v.w;
            int b = t / half;
            atomicAdd(&h[b * NBINS + score_bin(y)], 1);
            atomicAdd(&h[b * NBINS + score_bin(w)], 1);
        }
        sc[u * 2 + 0] = y;
        sc[u * 2 + 1] = w;
    }
    __syncthreads();
    for (int t = threadIdx.x; t < BATCH * NBINS; t += HS_THREADS)
        if (h[t]) atomicAdd(&g_hist[t], h[t]);

    __threadfence();
    __shared__ int is_last;
    if (threadIdx.x == 0)
        is_last = (atomicAdd(&g_ticket, 1u) == HS_BLOCKS - 1) ? 1 : 0;
    __syncthreads();

    if (is_last) {
        __shared__ int sA[1024], sB[1024];
        for (int b = 0; b < BATCH; ++b) {
            int t = threadIdx.x;
            int base = b * NBINS + t * 2;
            int h0 = g_hist[base + 0], h1 = g_hist[base + 1];
            int sum = h0 + h1;
            sA[t] = sum;
            __syncthreads();
            int* src = sA; int* dst = sB;
            for (int d = 1; d < 1024; d <<= 1) {
                int v = src[t];
                if (t + d < 1024) v += src[t + d];
                dst[t] = v;
                __syncthreads();
                int* tmp = src; src = dst; dst = tmp;
            }
            int excl = src[t] - sum;
            int off1 = excl;
            int off0 = off1 + h1;
            g_offset[base + 0] = off0; g_offset[base + 1] = off1;
            if (off1 + h1 >= PRE_NMS) atomicMax(&g_cutbin[b], t * 2 + 1);
            else if (off0 + h0 >= PRE_NMS) atomicMax(&g_cutbin[b], t * 2 + 0);
            __syncthreads();
        }
        __threadfence();
        if (threadIdx.x == 0) atomicExch(&g_ready, 1);
    }

    if (threadIdx.x == 0) {
        while (atomicAdd(&g_ready, 0) == 0) __nanosleep(128);
    }
    __syncthreads();
    __threadfence();

    int cut0 = g_cutbin[0];
    int cut1 = g_cutbin[1];
#pragma unroll
    for (int u = 0; u < HS_PER_THREAD; ++u) {
        int t = tid + u * gsz;
        if (t >= total4) continue;
        int b = t / half;
        int i0 = (t - b * half) * 2;
        int cut = (b == 0) ? cut0 : cut1;
#pragma unroll
        for (int e = 0; e < 2; ++e) {
            float s = sc[u * 2 + e];
            int i = i0 + e;
            int q = score_bin(s);
            if (q >= cut) {
                int pos = g_offset[b * NBINS + q] + atomicAdd(&g_binfill[b * NBINS + q], 1);
                if (pos < SCAP) {
                    unsigned int sb = __float_as_uint(s);
                    g_sorted[b * SCAP + pos] =
                        ((u64)sb << 32) | (u64)(0xFFFFFFFFu - (unsigned)i);
                }
            }
        }
    }
}

// ---------------- 2: per-bucket sort + box decode (cutbin-relative grid) -------
__global__ void sortbox_kernel(const float* __restrict__ rpn_bbox,
                               const float* __restrict__ anchors) {
    int b = blockIdx.y;
    int cut = g_cutbin[b];
    __shared__ u64 s[BUCKET_CAP];
    for (int bin = cut + blockIdx.x; bin < NBINS; bin += SB_GRID) {
        int cnt = g_hist[b * NBINS + bin];
        if (cnt <= 0) continue;
        if (cnt > BUCKET_CAP) cnt = BUCKET_CAP;
        int off = g_offset[b * NBINS + bin];
        if (off >= PRE_NMS) continue;
        int P = 1;
        while (P < cnt) P <<= 1;
        const u64* src = g_sorted + (size_t)b * SCAP + off;
        for (int t = threadIdx.x; t < P; t += blockDim.x)
            s[t] = (t < cnt) ? src[t] : 0ULL;
        __syncthreads();
        if (cnt > 1) {
            for (int k = 2; k <= P; k <<= 1) {
                for (int j = k >> 1; j > 0; j >>= 1) {
                    for (int i = threadIdx.x; i < P; i += blockDim.x) {
                        int ixj = i ^ j;
                        if (ixj > i) {
                            bool dir = ((i & k) == 0);
                            u64 a = s[i], c = s[ixj];
                            if ((a < c) == dir) { s[i] = c; s[ixj] = a; }
                        }
                    }
                    __syncthreads();
                }
            }
        }
        for (int t = threadIdx.x; t < cnt; t += blockDim.x) {
            int rank = off + t;
            if (rank >= PRE_NMS) continue;
            unsigned int low = (unsigned int)(s[t] & 0xFFFFFFFFu);
            int idx = (int)(0xFFFFFFFFu - low);
            size_t base = ((size_t)b * NANCH + (size_t)idx) * 4;
            float a0 = anchors[base + 0], a1 = anchors[base + 1];
            float a2 = anchors[base + 2], a3 = anchors[base + 3];
            float d0 = rpn_bbox[base + 0] * 0.1f;
            float d1 = rpn_bbox[base + 1] * 0.1f;
            float d2 = rpn_bbox[base + 2] * 0.2f;
            float d3 = rpn_bbox[base + 3] * 0.2f;
            float h = a2 - a0, w = a3 - a1;
            float cy = a0 + 0.5f * h + d0 * h;
            float cx = a1 + 0.5f * w + d1 * w;
            h = h * expf(d2);
            w = w * expf(d3);
            float y1 = cy - 0.5f * h;
            float x1 = cx - 0.5f * w;
            float y2 = y1 + h;
            float x2 = x1 + w;
            y1 = fminf(fmaxf(y1, 0.f), 1.f);
            x1 = fminf(fmaxf(x1, 0.f), 1.f);
            y2 = fminf(fmaxf(y2, 0.f), 1.f);
            x2 = fminf(fmaxf(x2, 0.f), 1.f);
            g_boxes[b * PRE_NMS + rank] = make_float4(y1, x1, y2, x2);
        }
        __syncthreads();
    }
}

// -- 3: prefix IoU bitmask + uncertain-row classification (lower triangle) ------
__global__ void __launch_bounds__(128) maskpre_kernel() {
    int b = blockIdx.z;
    int row0 = blockIdx.y * 128;
    int col0 = blockIdx.x * 64;
    if (col0 >= row0 + 128) return;   // no column <= any row-word in block
    __shared__ float4 cbox[64];
    __shared__ float cA7[64];
    int t = threadIdx.x;              // 128 threads
    if (t < 64) {
        float4 cb = g_boxes[b * PRE_NMS + col0 + t];
        cbox[t] = cb;
        cA7[t] = 0.7f * ((cb.z - cb.x) * (cb.w - cb.y) + 1e-8f);
    }
    __syncthreads();
    int r = row0 + t;
    float4 rb = g_boxes[b * PRE_NMS + r];
    float aR7 = 0.7f * ((rb.z - rb.x) * (rb.w - rb.y));
    unsigned lo = 0, hi = 0;
#pragma unroll
    for (int jj = 0; jj < 32; ++jj)
        if (iou_gt(rb, aR7, cbox[jj], cA7[jj])) lo |= (1u << jj);
#pragma unroll
    for (int jj = 0; jj < 32; ++jj)
        if (iou_gt(rb, aR7, cbox[32 + jj], cA7[32 + jj])) hi |= (1u << jj);
    u64 word = ((u64)hi << 32) | lo;
    g_mask2[((size_t)b * PRE2 + r) * NW2 + blockIdx.x] = word;
    // classify: any lower-triangle overlap -> row is "uncertain"
    int wi = r >> 6, k = blockIdx.x;
    u64 lower = (k < wi) ? word
              : ((k == wi) ? (word & ((1ULL << (r & 63)) - 1ULL)) : 0ULL);
    if (lower != 0ULL)
        atomicOr(&g_unc[b * (PRE2 / 32) + (r >> 5)], 1u << (r & 31));
}

// -- 4: NMS — certain free; parallel cert-check; serial only 2nd-order rows -----
__global__ void __launch_bounds__(256) nms_kernel(float* __restrict__ out) {
    if (blockIdx.x >= BATCH) {
        // cleanup blocks: re-zero scratch read by EARLIER kernels of the NEXT
        // replay only (cross-launch ordered; g_unc is zeroed in histscatter).
        int start = (blockIdx.x - BATCH) * blockDim.x + threadIdx.x;
        for (int t = start; t < BATCH * NBINS; t += 8 * blockDim.x) {
            g_hist[t] = 0;
            g_binfill[t] = 0;
        }
        if (start == 0) {
            g_cutbin[0] = 0; g_cutbin[1] = 0;
            g_ticket = 0u;
            g_ready = 0;
        }
        return;
    }
    int b = blockIdx.x;
    extern __shared__ unsigned char dynsm[];
    u64* urows = (u64*)dynsm;          // [UCAP][NW2] gathered uncertain rows
    __shared__ u64 keptW[NW2];
    __shared__ short ulist[UCAP];
    __shared__ unsigned so_bm[UCAP / 32];   // second-order candidate bitmap
    __shared__ short so_list[UCAP];
    __shared__ int s_U, s_NS, s_kc;
    __shared__ int wpfx[NW2];
    __shared__ int list[PROP];
    int tid = threadIdx.x;

    // build keptW (certain rows kept) and the ordered uncertain list
    if (tid == 0) {
        int n = 0;
        for (int w = 0; w < NW2; ++w) {
            unsigned u0 = g_unc[b * (PRE2 / 32) + 2 * w];
            unsigned u1 = g_unc[b * (PRE2 / 32) + 2 * w + 1];
            u64 un = (u64)u0 | ((u64)u1 << 32);
            keptW[w] = ~un;
            while (un && n < UCAP) {
                int bit = __ffsll((long long)un) - 1;
                ulist[n++] = (short)(w * 64 + bit);
                un &= un - 1;
            }
            if (un) { n = UCAP + 1; break; }   // overflow -> fallback
        }
        s_U = n;
    }
    for (int t = tid; t < UCAP / 32; t += 256) so_bm[t] = 0u;
    __syncthreads();
    int U = s_U;
    bool resolved = (U <= UCAP);

    if (resolved) {
        // gather uncertain rows' mask words from L2 (parallel, ~U*20 loads)
        const u64* M = g_mask2 + (size_t)b * PRE2 * NW2;
        for (int idx = tid; idx < U * NW2; idx += 256) {
            int u = idx / NW2;
            int w = idx - u * NW2;
            urows[u * NW2 + w] = M[(size_t)ulist[u] * NW2 + w];
        }
        __syncthreads();

        // first-order check (parallel): overlap with any certain kept row
        // => definitively suppressed. Otherwise second-order candidate.
        for (int u = tid; u < U; u += 256) {
            int i = ulist[u];
            int wi = i >> 6;
            const u64* rp = urows + u * NW2;
            u64 ov = 0;
            for (int w = 0; w < wi; ++w) ov |= rp[w] & keptW[w];
            ov |= rp[wi] & keptW[wi] & ((1ULL << (i & 63)) - 1ULL);
            if (ov == 0ULL)
                atomicOr(&so_bm[u >> 5], 1u << (u & 31));
        }
        __syncthreads();
        if (tid == 0) {
            int ns = 0;
            for (int w = 0; w < UCAP / 32; ++w) {
                unsigned m = so_bm[w];
                while (m) {
                    int bit = __ffs((int)m) - 1;
                    so_list[ns++] = (short)(w * 32 + bit);
                    m &= m - 1;
                }
            }
            s_NS = ns;
        }
        __syncthreads();
        int NS = s_NS;
        if (tid < 32) {
            // serial tail: resolve only second-order rows in rank order
            int lane = tid;
            u64 kw = (lane < NW2) ? keptW[lane] : 0ULL;
            for (int q = 0; q < NS; ++q) {
                int u = so_list[q];
                int i = ulist[u];
                int wi = i >> 6;
                u64 cur = (lane < NW2) ? urows[u * NW2 + lane] : 0ULL;
                u64 m = (lane < wi) ? cur
                       : ((lane == wi) ? (cur & ((1ULL << (i & 63)) - 1ULL)) : 0ULL);
                bool sup = __any_sync(0xffffffffu, (m & kw) != 0ULL);
                if (!sup && lane == wi) kw |= (1ULL << (i & 63));
            }
            if (lane < NW2) keptW[lane] = kw;
        }
    }
    __syncthreads();

    if (tid == 0) {
        if (!resolved) {
            s_kc = 0;                   // exact fallback will handle it
        } else {
            int acc = 0;
            for (int w = 0; w < NW2; ++w) { wpfx[w] = acc; acc += __popcll(keptW[w]); }
            s_kc = acc;
        }
    }
    __syncthreads();

    int kc = s_kc;
    const float4* bx = g_boxes + b * PRE_NMS;
    float4* o = (float4*)(out + (size_t)b * PROP * 4);
    if (kc >= PROP) {
        for (int i = tid; i < PRE2; i += 256) {
            int wi = i >> 6;
            u64 kwv = keptW[wi];
            if ((kwv >> (i & 63)) & 1ULL) {
                int pos = wpfx[wi] + __popcll(kwv & ((1ULL << (i & 63)) - 1ULL));
                if (pos < PROP) list[pos] = i;
            }
        }
        __syncthreads();
        for (int r = tid; r < PROP; r += 256) o[r] = bx[list[r]];
        return;
    }

    // fallback: exact direct sequential NMS over all 6000 boxes (rarely taken)
    float4* kept = (float4*)dynsm;
    float* keptA7 = (float*)(dynsm + sizeof(float4) * PROP);
    __syncthreads();
    int kk = 0;
    for (int i = 0; i < PRE_NMS && kk < PROP; ++i) {
        float4 bi = bx[i];
        float aR7 = 0.7f * ((bi.z - bi.x) * (bi.w - bi.y));
        int sup = 0;
        for (int j = tid; j < kk; j += 256)
            if (iou_gt(bi, aR7, kept[j], keptA7[j])) sup = 1;
        sup = __syncthreads_or(sup);
        if (!sup) {
            if (tid == 0) {
                kept[kk] = bi;
                keptA7[kk] = 0.7f * ((bi.z - bi.x) * (bi.w - bi.y) + 1e-8f);
            }
            kk++;
            __syncthreads();
        }
    }
    for (int r = tid; r < PROP; r += 256) {
        float4 v = make_float4(0.f, 0.f, 0.f, 0.f);
        if (r < kk) v = kept[r];
        o[r] = v;
    }
}

// ---------------- launch ----------------
extern "C" void kernel_launch(void* const* d_in, const int* in_sizes, int n_in,
                              void* d_out, int out_size) {
    (void)in_sizes; (void)n_in; (void)out_size;
    const float4* cls4 = (const float4*)d_in[0];
    const float* rpn_bbox = (const float*)d_in[1];
    const float* anchors = (const float*)d_in[2];
    float* out = (float*)d_out;

    cudaFuncSetAttribute(nms_kernel, cudaFuncAttributeMaxDynamicSharedMemorySize,
                         SMEM_NMS);

    histscatter_kernel<<<HS_BLOCKS, HS_THREADS>>>(cls4);
    {
        dim3 grid(SB_GRID, BATCH);
        sortbox_kernel<<<grid, 128>>>(rpn_bbox, anchors);
    }
    {
        dim3 grid(NW2, PRE2 / 128, BATCH);   // (20, 10, 2)
        maskpre_kernel<<<grid, 128>>>();
    }
    nms_kernel<<<BATCH + 8, 256, SMEM_NMS>>>(out);
}

// round 17
// speedup vs baseline: 2.0360x; 1.0060x over previous
#include <cuda_runtime.h>
#include <cuda_bf16.h>
#include <cstdint>

#define BATCH 2
#define NANCH 261888
#define PRE_NMS 6000
#define PRE2 1280          // prefix length for fast-path NMS
#define NW2 (PRE2 / 64)    // 20 words per prefix row
#define PROP 1000
#define NMS_THR 0.7f
#define NBINS 2048
#define SCAP 12288
#define BUCKET_CAP 2048
#define SM_BLOCKS 256      // fused sortmask grid (must be co-resident)
#define UCAP 512           // max uncertain rows handled by fast path

#define HS_BLOCKS 128
#define HS_THREADS 1024
#define HS_PER_THREAD 2    // float4s per thread: 128*1024*2 = 262144 >= 261888

#define SMEM_NMS (UCAP * NW2 * 8)   // 81920 B gathered uncertain rows

typedef unsigned long long u64;

// ---------------- scratch (zero at module load; re-zeroed across launches) ------
__device__ int g_hist[BATCH * NBINS];
__device__ int g_offset[BATCH * NBINS];
__device__ int g_binfill[BATCH * NBINS];
__device__ int g_cutbin[BATCH];
__device__ unsigned int g_ticket;
__device__ unsigned int g_tick2;
__device__ int g_ready;
__device__ unsigned g_unc[BATCH * (PRE2 / 32)];   // uncertain-row bitmap (80 words)
__device__ u64 g_sorted[BATCH * SCAP];
__device__ float4 g_boxes[BATCH * PRE_NMS];
__device__ u64 g_mask2[(size_t)BATCH * PRE2 * NW2];   // 400 KB prefix mask

// ---------------- helpers ----------------
__device__ __forceinline__ int score_bin(float s) {
    int b = (int)(s * (float)NBINS);
    if (b < 0) b = 0;
    if (b > NBINS - 1) b = NBINS - 1;
    return b;
}

// keep ⟺ iou > THR ⟺ (1+THR)*inter > THR*(areaR+areaC+eps)  (denominator > 0)
__device__ __forceinline__ bool iou_gt(float4 a, float aR7, float4 c, float cA7) {
    float ih = fmaxf(fminf(a.z, c.z) - fmaxf(a.x, c.x), 0.f);
    float iw = fmaxf(fminf(a.w, c.w) - fmaxf(a.y, c.y), 0.f);
    float inter = ih * iw;
    return 1.7f * inter > aR7 + cA7;
}

// ------ 1: fused histogram + suffix-scan + scatter (single read of cls) --------
// Also zeroes g_unc and g_tick2 for this replay (written/used by later kernels
// of the SAME replay — strict launch ordering, no race).
__global__ void __launch_bounds__(HS_THREADS, 1)
histscatter_kernel(const float4* __restrict__ cls4) {
    if (threadIdx.x < BATCH * (PRE2 / 32))
        g_unc[threadIdx.x] = 0u;
    if (threadIdx.x == HS_THREADS - 1)
        g_tick2 = 0u;
    __shared__ int h[BATCH * NBINS];   // 16 KB
    for (int t = threadIdx.x; t < BATCH * NBINS; t += HS_THREADS) h[t] = 0;
    __syncthreads();
    const int total4 = BATCH * NANCH / 2;   // 261888
    const int half = NANCH / 2;
    const int gsz = HS_BLOCKS * HS_THREADS; // 131072
    int tid = blockIdx.x * HS_THREADS + threadIdx.x;

    float sc[HS_PER_THREAD * 2];
#pragma unroll
    for (int u = 0; u < HS_PER_THREAD; ++u) {
        int t = tid + u * gsz;
        float y = -1.f, w = -1.f;
        if (t < total4) {
            float4 v = cls4[t];
            y = v.y; w = v.w;
            int b = t / half;
            atomicAdd(&h[b * NBINS + score_bin(y)], 1);
            atomicAdd(&h[b * NBINS + score_bin(w)], 1);
        }
        sc[u * 2 + 0] = y;
        sc[u * 2 + 1] = w;
    }
    __syncthreads();
    for (int t = threadIdx.x; t < BATCH * NBINS; t += HS_THREADS)
        if (h[t]) atomicAdd(&g_hist[t], h[t]);

    __threadfence();
    __shared__ int is_last;
    if (threadIdx.x == 0)
        is_last = (atomicAdd(&g_ticket, 1u) == HS_BLOCKS - 1) ? 1 : 0;
    __syncthreads();

    if (is_last) {
        __shared__ int sA[1024], sB[1024];
        for (int b = 0; b < BATCH; ++b) {
            int t = threadIdx.x;
            int base = b * NBINS + t * 2;
            int h0 = g_hist[base + 0], h1 = g_hist[base + 1];
            int sum = h0 + h1;
            sA[t] = sum;
            __syncthreads();
            int* src = sA; int* dst = sB;
            for (int d = 1; d < 1024; d <<= 1) {
                int v = src[t];
                if (t + d < 1024) v += src[t + d];
                dst[t] = v;
                __syncthreads();
                int* tmp = src; src = dst; dst = tmp;
            }
            int excl = src[t] - sum;
            int off1 = excl;
            int off0 = off1 + h1;
            g_offset[base + 0] = off0; g_offset[base + 1] = off1;
            if (off1 + h1 >= PRE_NMS) atomicMax(&g_cutbin[b], t * 2 + 1);
            else if (off0 + h0 >= PRE_NMS) atomicMax(&g_cutbin[b], t * 2 + 0);
            __syncthreads();
        }
        __threadfence();
        if (threadIdx.x == 0) atomicExch(&g_ready, 1);
    }

    if (threadIdx.x == 0) {
        while (atomicAdd(&g_ready, 0) == 0) __nanosleep(128);
    }
    __syncthreads();
    __threadfence();

    int cut0 = g_cutbin[0];
    int cut1 = g_cutbin[1];
#pragma unroll
    for (int u = 0; u < HS_PER_THREAD; ++u) {
        int t = tid + u * gsz;
        if (t >= total4) continue;
        int b = t / half;
        int i0 = (t - b * half) * 2;
        int cut = (b == 0) ? cut0 : cut1;
#pragma unroll
        for (int e = 0; e < 2; ++e) {
            float s = sc[u * 2 + e];
            int i = i0 + e;
            int q = score_bin(s);
            if (q >= cut) {
                int pos = g_offset[b * NBINS + q] + atomicAdd(&g_binfill[b * NBINS + q], 1);
                if (pos < SCAP) {
                    unsigned int sb = __float_as_uint(s);
                    g_sorted[b * SCAP + pos] =
                        ((u64)sb << 32) | (u64)(0xFFFFFFFFu - (unsigned)i);
                }
            }
        }
    }
}

// --- 2: FUSED per-bucket sort + box decode, grid sync, IoU mask + classify -----
__global__ void __launch_bounds__(128) sortmask_kernel(
    const float* __restrict__ rpn_bbox, const float* __restrict__ anchors) {
    __shared__ u64 s[BUCKET_CAP];   // 16 KB (sort phase)
    int tidx = threadIdx.x;

    // ---- phase 1: bucket sort + box decode (identical work split to R16) ----
    {
        int b = blockIdx.x >> 7;          // 0..1
        int blkin = blockIdx.x & 127;     // 0..127
        int cut = g_cutbin[b];
        for (int bin = cut + blkin; bin < NBINS; bin += 128) {
            int cnt = g_hist[b * NBINS + bin];
            if (cnt <= 0) continue;
            if (cnt > BUCKET_CAP) cnt = BUCKET_CAP;
            int off = g_offset[b * NBINS + bin];
            if (off >= PRE_NMS) continue;
            int P = 1;
            while (P < cnt) P <<= 1;
            const u64* src = g_sorted + (size_t)b * SCAP + off;
            for (int t = tidx; t < P; t += 128)
                s[t] = (t < cnt) ? src[t] : 0ULL;
            __syncthreads();
            if (cnt > 1) {
                for (int k = 2; k <= P; k <<= 1) {
                    for (int j = k >> 1; j > 0; j >>= 1) {
                        for (int i = tidx; i < P; i += 128) {
                            int ixj = i ^ j;
                            if (ixj > i) {
                                bool dir = ((i & k) == 0);
                                u64 a = s[i], c = s[ixj];
                                if ((a < c) == dir) { s[i] = c; s[ixj] = a; }
                            }
                        }
                        __syncthreads();
                    }
                }
            }
            for (int t = tidx; t < cnt; t += 128) {
                int rank = off + t;
                if (rank >= PRE_NMS) continue;
                unsigned int low = (unsigned int)(s[t] & 0xFFFFFFFFu);
                int idx = (int)(0xFFFFFFFFu - low);
                size_t base = ((size_t)b * NANCH + (size_t)idx) * 4;
                float a0 = anchors[base + 0], a1 = anchors[base + 1];
                float a2 = anchors[base + 2], a3 = anchors[base + 3];
                float d0 = rpn_bbox[base + 0] * 0.1f;
                float d1 = rpn_bbox[base + 1] * 0.1f;
                float d2 = rpn_bbox[base + 2] * 0.2f;
                float d3 = rpn_bbox[base + 3] * 0.2f;
                float h = a2 - a0, w = a3 - a1;
                float cy = a0 + 0.5f * h + d0 * h;
                float cx = a1 + 0.5f * w + d1 * w;
                h = h * expf(d2);
                w = w * expf(d3);
                float y1 = cy - 0.5f * h;
                float x1 = cx - 0.5f * w;
                float y2 = y1 + h;
                float x2 = x1 + w;
                y1 = fminf(fmaxf(y1, 0.f), 1.f);
                x1 = fminf(fmaxf(x1, 0.f), 1.f);
                y2 = fminf(fmaxf(y2, 0.f), 1.f);
                x2 = fminf(fmaxf(x2, 0.f), 1.f);
                g_boxes[b * PRE_NMS + rank] = make_float4(y1, x1, y2, x2);
            }
            __syncthreads();
        }
    }

    // ---- grid sync: all SM_BLOCKS co-resident (2/SM needed, 13 allowed) -----
    __threadfence();
    if (tidx == 0) {
        atomicAdd(&g_tick2, 1u);
        while (atomicAdd(&g_tick2, 0u) < (unsigned)SM_BLOCKS) __nanosleep(64);
    }
    __syncthreads();
    __threadfence();

    // ---- phase 2: IoU bitmask + uncertain classification (lower triangle) ---
    float4* cbox = (float4*)s;                 // reuse sort smem
    float* cA7 = (float*)(cbox + 64);
    const int ROWG = PRE2 / 128;               // 10 row-groups
    const int NTILES = NW2 * ROWG * BATCH;     // 400 tiles
    for (int tile = blockIdx.x; tile < NTILES; tile += SM_BLOCKS) {
        int k = tile % NW2;
        int rg = (tile / NW2) % ROWG;
        int b = tile / (NW2 * ROWG);
        int row0 = rg * 128;
        int col0 = k * 64;
        if (col0 >= row0 + 128) continue;      // no column <= any row-word
        __syncthreads();
        if (tidx < 64) {
            float4 cb = g_boxes[b * PRE_NMS + col0 + tidx];
            cbox[tidx] = cb;
            cA7[tidx] = 0.7f * ((cb.z - cb.x) * (cb.w - cb.y) + 1e-8f);
        }
        __syncthreads();
        int r = row0 + tidx;
        float4 rb = g_boxes[b * PRE_NMS + r];
        float aR7 = 0.7f * ((rb.z - rb.x) * (rb.w - rb.y));
        unsigned lo = 0, hi = 0;
#pragma unroll
        for (int jj = 0; jj < 32; ++jj)
            if (iou_gt(rb, aR7, cbox[jj], cA7[jj])) lo |= (1u << jj);
#pragma unroll
        for (int jj = 0; jj < 32; ++jj)
            if (iou_gt(rb, aR7, cbox[32 + jj], cA7[32 + jj])) hi |= (1u << jj);
        u64 word = ((u64)hi << 32) | lo;
        g_mask2[((size_t)b * PRE2 + r) * NW2 + k] = word;
        int wi = r >> 6;
        u64 lower = (k < wi) ? word
                  : ((k == wi) ? (word & ((1ULL << (r & 63)) - 1ULL)) : 0ULL);
        if (lower != 0ULL)
            atomicOr(&g_unc[b * (PRE2 / 32) + (r >> 5)], 1u << (r & 31));
    }
}

// -- 3: NMS — certain free; parallel cert-check; serial only 2nd-order rows -----
__global__ void __launch_bounds__(256) nms_kernel(float* __restrict__ out) {
    if (blockIdx.x >= BATCH) {
        // cleanup blocks: re-zero scratch read by EARLIER kernels of the NEXT
        // replay only (cross-launch ordered; g_unc/g_tick2 zeroed in histscatter).
        int start = (blockIdx.x - BATCH) * blockDim.x + threadIdx.x;
        for (int t = start; t < BATCH * NBINS; t += 8 * blockDim.x) {
            g_hist[t] = 0;
            g_binfill[t] = 0;
        }
        if (start == 0) {
            g_cutbin[0] = 0; g_cutbin[1] = 0;
            g_ticket = 0u;
            g_ready = 0;
        }
        return;
    }
    int b = blockIdx.x;
    extern __shared__ unsigned char dynsm[];
    u64* urows = (u64*)dynsm;          // [UCAP][NW2] gathered uncertain rows
    __shared__ unsigned s_unc[PRE2 / 32];
    __shared__ u64 keptW[NW2];
    __shared__ short ulist[UCAP];
    __shared__ unsigned so_bm[UCAP / 32];   // second-order candidate bitmap
    __shared__ short so_list[UCAP];
    __shared__ int s_U, s_NS, s_kc;
    __shared__ int wpfx[NW2];
    __shared__ int list[PROP];
    int tid = threadIdx.x;

    // preload g_unc via parallel threads (kills thread-0 serial L2 walk)
    if (tid < PRE2 / 32) s_unc[tid] = g_unc[b * (PRE2 / 32) + tid];
    for (int t = tid; t < UCAP / 32; t += 256) so_bm[t] = 0u;
    __syncthreads();

    // build keptW (certain rows kept) and the ordered uncertain list (from LDS)
    if (tid == 0) {
        int n = 0;
        for (int w = 0; w < NW2; ++w) {
            u64 un = (u64)s_unc[2 * w] | ((u64)s_unc[2 * w + 1] << 32);
            keptW[w] = ~un;
            while (un && n < UCAP) {
                int bit = __ffsll((long long)un) - 1;
                ulist[n++] = (short)(w * 64 + bit);
                un &= un - 1;
            }
            if (un) { n = UCAP + 1; break; }   // overflow -> fallback
        }
        s_U = n;
    }
    __syncthreads();
    int U = s_U;
    bool resolved = (U <= UCAP);

    if (resolved) {
        // gather uncertain rows' mask words from L2 (parallel, ~U*20 loads)
        const u64* M = g_mask2 + (size_t)b * PRE2 * NW2;
        for (int idx = tid; idx < U * NW2; idx += 256) {
            int u = idx / NW2;
            int w = idx - u * NW2;
            urows[u * NW2 + w] = M[(size_t)ulist[u] * NW2 + w];
        }
        __syncthreads();

        // first-order check (parallel): overlap with any certain kept row
        for (int u = tid; u < U; u += 256) {
            int i = ulist[u];
            int wi = i >> 6;
            const u64* rp = urows + u * NW2;
            u64 ov = 0;
            for (int w = 0; w < wi; ++w) ov |= rp[w] & keptW[w];
            ov |= rp[wi] & keptW[wi] & ((1ULL << (i & 63)) - 1ULL);
            if (ov == 0ULL)
                atomicOr(&so_bm[u >> 5], 1u << (u & 31));
        }
        __syncthreads();
        if (tid == 0) {
            int ns = 0;
            for (int w = 0; w < UCAP / 32; ++w) {
                unsigned m = so_bm[w];
                while (m) {
                    int bit = __ffs((int)m) - 1;
                    so_list[ns++] = (short)(w * 32 + bit);
                    m &= m - 1;
                }
            }
            s_NS = ns;
        }
        __syncthreads();
        int NS = s_NS;
        if (tid < 32) {
            // serial tail: resolve only second-order rows in rank order
            int lane = tid;
            u64 kw = (lane < NW2) ? keptW[lane] : 0ULL;
            for (int q = 0; q < NS; ++q) {
                int u = so_list[q];
                int i = ulist[u];
                int wi = i >> 6;
                u64 cur = (lane < NW2) ? urows[u * NW2 + lane] : 0ULL;
                u64 m = (lane < wi) ? cur
                       : ((lane == wi) ? (cur & ((1ULL << (i & 63)) - 1ULL)) : 0ULL);
                bool sup = __any_sync(0xffffffffu, (m & kw) != 0ULL);
                if (!sup && lane == wi) kw |= (1ULL << (i & 63));
            }
            if (lane < NW2) keptW[lane] = kw;
        }
    }
    __syncthreads();

    if (tid == 0) {
        if (!resolved) {
            s_kc = 0;                   // exact fallback will handle it
        } else {
            int acc = 0;
            for (int w = 0; w < NW2; ++w) { wpfx[w] = acc; acc += __popcll(keptW[w]); }
            s_kc = acc;
        }
    }
    __syncthreads();

    int kc = s_kc;
    const float4* bx = g_boxes + b * PRE_NMS;
    float4* o = (float4*)(out + (size_t)b * PROP * 4);
    if (kc >= PROP) {
        for (int i = tid; i < PRE2; i += 256) {
            int wi = i >> 6;
            u64 kwv = keptW[wi];
            if ((kwv >> (i & 63)) & 1ULL) {
                int pos = wpfx[wi] + __popcll(kwv & ((1ULL << (i & 63)) - 1ULL));
                if (pos < PROP) list[pos] = i;
            }
        }
        __syncthreads();
        for (int r = tid; r < PROP; r += 256) o[r] = bx[list[r]];
        return;
    }

    // fallback: exact direct sequential NMS over all 6000 boxes (rarely taken)
    float4* kept = (float4*)dynsm;
    float* keptA7 = (float*)(dynsm + sizeof(float4) * PROP);
    __syncthreads();
    int kk = 0;
    for (int i = 0; i < PRE_NMS && kk < PROP; ++i) {
        float4 bi = bx[i];
        float aR7 = 0.7f * ((bi.z - bi.x) * (bi.w - bi.y));
        int sup = 0;
        for (int j = tid; j < kk; j += 256)
            if (iou_gt(bi, aR7, kept[j], keptA7[j])) sup = 1;
        sup = __syncthreads_or(sup);
        if (!sup) {
            if (tid == 0) {
                kept[kk] = bi;
                keptA7[kk] = 0.7f * ((bi.z - bi.x) * (bi.w - bi.y) + 1e-8f);
            }
            kk++;
            __syncthreads();
        }
    }
    for (int r = tid; r < PROP; r += 256) {
        float4 v = make_float4(0.f, 0.f, 0.f, 0.f);
        if (r < kk) v = kept[r];
        o[r] = v;
    }
}

// ---------------- launch ----------------
extern "C" void kernel_launch(void* const* d_in, const int* in_sizes, int n_in,
                              void* d_out, int out_size) {
    (void)in_sizes; (void)n_in; (void)out_size;
    const float4* cls4 = (const float4*)d_in[0];
    const float* rpn_bbox = (const float*)d_in[1];
    const float* anchors = (const float*)d_in[2];
    float* out = (float*)d_out;

    cudaFuncSetAttribute(nms_kernel, cudaFuncAttributeMaxDynamicSharedMemorySize,
                         SMEM_NMS);

    histscatter_kernel<<<HS_BLOCKS, HS_THREADS>>>(cls4);
    sortmask_kernel<<<SM_BLOCKS, 128>>>(rpn_bbox, anchors);
    nms_kernel<<<BATCH + 8, 256, SMEM_NMS>>>(out);
}